// round 9
// baseline (speedup 1.0000x reference)
#include <cuda_runtime.h>

#define C_ATOM 128
#define C_REF  389
#define C_PAIR 16
#define CL_ROWS 8          // rows per cl block (8 warps x 1 row)
#define PLM_ITERS 4        // 128 pairs/iter * 4 = 512 pairs/block

// ---------------------------------------------------------------------------
// Fused kernel.
// Blocks [0, plmBlocks):       plm, 512 pairs/block, 2 threads/pair.
//   Phase A: 4 independent uid LDGs, then 4 UNCONDITIONAL zero
//            st.global.cs.v8.f32 (32B/thread, 1024B contiguous per warp
//            instruction) -> memset-like store stream with zero dependencies.
//   Phase B: rare (~0.4%) matching slots recomputed + re-stored by the same
//            thread (program order to same address -> nonzero value wins).
// Blocks [plmBlocks, +clBlocks): cl = feats @ W_feats + b_feats.
//   Placed LAST so the store stream starts at t=0 and cl's FMA tail overlaps
//   the final store drain.
// ---------------------------------------------------------------------------
__global__ void __launch_bounds__(256, 8)
fused_kernel(const float* __restrict__ pos,
             const float* __restrict__ charge,
             const float* __restrict__ mask,
             const float* __restrict__ elem,
             const float* __restrict__ names,
             const int*   __restrict__ uid,
             const float* __restrict__ Wf,
             const float* __restrict__ bf,
             const float* __restrict__ Woff,
             const float* __restrict__ boff,
             const float* __restrict__ Winv,
             const float* __restrict__ binv,
             const float* __restrict__ Wvm,
             const float* __restrict__ bvm,
             float* __restrict__ out, int N, int plmBlocks)
{
    __shared__ float sf[CL_ROWS][C_REF];

    const int tid = threadIdx.x;

    if (blockIdx.x >= (unsigned)plmBlocks) {
        // ------------------------- cl path (last blocks) --------------------
        const int n0   = (blockIdx.x - plmBlocks) * CL_ROWS;
        const int warp = tid >> 5;
        const int lane = tid & 31;

        for (int idx = tid; idx < CL_ROWS * C_REF; idx += 256) {
            int r = idx / C_REF;
            int j = idx - r * C_REF;
            int n = n0 + r;
            float v;
            if (j < 3)        v = pos[n * 3 + j];
            else if (j == 3)  v = charge[n];
            else if (j == 4)  v = mask[n];
            else if (j < 133) v = elem[n * 128 + (j - 5)];
            else              v = names[n * 256 + (j - 133)];
            sf[r][j] = v;
        }
        __syncthreads();

        const int c4 = lane * 4;
        float4 acc = *reinterpret_cast<const float4*>(bf + c4);

#pragma unroll 4
        for (int j = 0; j < C_REF; j++) {
            float4 w = *reinterpret_cast<const float4*>(Wf + j * C_ATOM + c4);
            float  f = sf[warp][j];
            acc.x = fmaf(w.x, f, acc.x);
            acc.y = fmaf(w.y, f, acc.y);
            acc.z = fmaf(w.z, f, acc.z);
            acc.w = fmaf(w.w, f, acc.w);
        }
        *reinterpret_cast<float4*>(out + (long long)(n0 + warp) * C_ATOM + c4) = acc;
        return;
    }

    // --------------------------- plm path ----------------------------------
    const int pair = tid >> 1;           // 0..127 within each iter
    const int kg0  = (tid & 1) * 8;      // channel half: 0 or 8

    const long long pbase = (long long)blockIdx.x * (128 * PLM_ITERS);
    const int l  = (int)(pbase / N);
    const int m0 = (int)(pbase - (long long)l * N) + pair;

    const int ul = __ldg(uid + l);

    float* op = out + (long long)N * C_ATOM + (pbase + pair) * C_PAIR + kg0;

    // Phase A: batch independent uid loads ...
    int um[PLM_ITERS];
#pragma unroll
    for (int it = 0; it < PLM_ITERS; it++)
        um[it] = __ldg(uid + m0 + it * 128);

    // ... and dependency-free 256-bit zero stores (1KB/warp instruction).
#pragma unroll
    for (int it = 0; it < PLM_ITERS; it++) {
        float* p = op + (long long)it * (128 * C_PAIR);
        asm volatile(
            "st.global.cs.v8.f32 [%0], {%1, %1, %1, %1, %1, %1, %1, %1};"
            :: "l"(p), "f"(0.0f) : "memory");
    }

    // Phase B: rare overwrites (~0.4% of pairs).
#pragma unroll
    for (int it = 0; it < PLM_ITERS; it++) {
        if (um[it] == ul) {
            const int m = m0 + it * 128;
            const float d0 = __ldg(pos + l * 3 + 0) - __ldg(pos + m * 3 + 0);
            const float d1 = __ldg(pos + l * 3 + 1) - __ldg(pos + m * 3 + 1);
            const float d2 = __ldg(pos + l * 3 + 2) - __ldg(pos + m * 3 + 2);
            float s = fmaf(d0, d0, 1.0f);
            s = fmaf(d1, d1, s);
            s = fmaf(d2, d2, s);
            const float inv = __fdividef(1.0f, s);

            float acc[8];
#pragma unroll
            for (int q = 0; q < 8; q++) {
                const int c = kg0 + q;
                float t = __ldg(boff + c) + __ldg(binv + c)
                        + __ldg(Wvm + c) + __ldg(bvm + c);
                t = fmaf(d0,  __ldg(Woff + c),              t);
                t = fmaf(d1,  __ldg(Woff + C_PAIR + c),     t);
                t = fmaf(d2,  __ldg(Woff + 2 * C_PAIR + c), t);
                t = fmaf(inv, __ldg(Winv + c),              t);
                acc[q] = t;
            }
            float* p = op + (long long)it * (128 * C_PAIR);
            asm volatile(
                "st.global.cs.v8.f32 [%0], {%1, %2, %3, %4, %5, %6, %7, %8};"
                :: "l"(p), "f"(acc[0]), "f"(acc[1]), "f"(acc[2]), "f"(acc[3]),
                   "f"(acc[4]), "f"(acc[5]), "f"(acc[6]), "f"(acc[7])
                : "memory");
        }
    }
}

// ---------------------------------------------------------------------------
// Launch: single kernel; 8192 plm blocks FIRST, then 256 cl blocks.
// ---------------------------------------------------------------------------
extern "C" void kernel_launch(void* const* d_in, const int* in_sizes, int n_in,
                              void* d_out, int out_size)
{
    const float* pos    = (const float*)d_in[0];
    const float* charge = (const float*)d_in[1];
    const float* maskp  = (const float*)d_in[2];
    const float* elem   = (const float*)d_in[3];
    const float* names  = (const float*)d_in[4];
    const int*   uid    = (const int*)  d_in[5];
    const float* Wf     = (const float*)d_in[6];
    const float* bf     = (const float*)d_in[7];
    const float* Woff   = (const float*)d_in[8];
    const float* boff   = (const float*)d_in[9];
    const float* Winv   = (const float*)d_in[10];
    const float* binv   = (const float*)d_in[11];
    const float* Wvm    = (const float*)d_in[12];
    const float* bvm    = (const float*)d_in[13];

    const int N = in_sizes[1];  // B*N with B=1
    float* out = (float*)d_out;

    const long long pairs = (long long)N * N;
    const int plmBlocks = (int)(pairs / (128 * PLM_ITERS));     // 8192
    const int clBlocks  = N / CL_ROWS;                          // 256

    fused_kernel<<<plmBlocks + clBlocks, 256>>>(
        pos, charge, maskp, elem, names, uid, Wf, bf,
        Woff, boff, Winv, binv, Wvm, bvm, out, N, plmBlocks);
}

// round 10
// speedup vs baseline: 1.0643x; 1.0643x over previous
#include <cuda_runtime.h>

#define C_ATOM 128
#define C_REF  389
#define C_PAIR 16
#define CL_ROWS 8          // rows per cl block (8 warps x 1 row)
#define PLM_ITERS 8        // 64 pairs/iter * 8 = 512 pairs/block

// ---------------------------------------------------------------------------
// Fused kernel (R8 skeleton, cl blocks moved to the END of the grid).
//
// Blocks [0, plmBlocks): plm, 512 pairs/block, 4 threads/pair.
//   Phase A: 8 independent uid LDGs + 8 UNCONDITIONAL zero STG.cs.128
//            (no data/addr dependencies -> memset-like store issue).
//   Phase B: rare (~0.4%) matching slots recomputed and re-stored by the
//            same thread (program order to same address -> nonzero wins).
// Blocks [plmBlocks, +clBlocks): cl = feats @ W_feats + b_feats.
//   Runs last: plm store stream starts at full width at t=0; cl's FMA work
//   overlaps the final store drain.
// ---------------------------------------------------------------------------
__global__ void __launch_bounds__(256, 8)
fused_kernel(const float* __restrict__ pos,
             const float* __restrict__ charge,
             const float* __restrict__ mask,
             const float* __restrict__ elem,
             const float* __restrict__ names,
             const int*   __restrict__ uid,
             const float* __restrict__ Wf,
             const float* __restrict__ bf,
             const float* __restrict__ Woff,
             const float* __restrict__ boff,
             const float* __restrict__ Winv,
             const float* __restrict__ binv,
             const float* __restrict__ Wvm,
             const float* __restrict__ bvm,
             float* __restrict__ out, int N, int plmBlocks)
{
    __shared__ float sf[CL_ROWS][C_REF];

    const int tid = threadIdx.x;

    if (blockIdx.x >= (unsigned)plmBlocks) {
        // ------------------------- cl path (last blocks) --------------------
        const int n0   = (blockIdx.x - plmBlocks) * CL_ROWS;
        const int warp = tid >> 5;
        const int lane = tid & 31;

        for (int idx = tid; idx < CL_ROWS * C_REF; idx += 256) {
            int r = idx / C_REF;
            int j = idx - r * C_REF;
            int n = n0 + r;
            float v;
            if (j < 3)        v = pos[n * 3 + j];
            else if (j == 3)  v = charge[n];
            else if (j == 4)  v = mask[n];
            else if (j < 133) v = elem[n * 128 + (j - 5)];
            else              v = names[n * 256 + (j - 133)];
            sf[r][j] = v;
        }
        __syncthreads();

        const int c4 = lane * 4;
        float4 acc = *reinterpret_cast<const float4*>(bf + c4);

#pragma unroll 4
        for (int j = 0; j < C_REF; j++) {
            float4 w = *reinterpret_cast<const float4*>(Wf + j * C_ATOM + c4);
            float  f = sf[warp][j];
            acc.x = fmaf(w.x, f, acc.x);
            acc.y = fmaf(w.y, f, acc.y);
            acc.z = fmaf(w.z, f, acc.z);
            acc.w = fmaf(w.w, f, acc.w);
        }
        *reinterpret_cast<float4*>(out + (long long)(n0 + warp) * C_ATOM + c4) = acc;
        return;
    }

    // --------------------------- plm path ----------------------------------
    const int pair = tid >> 2;           // 0..63
    const int kg   = (tid & 3) * 4;      // 0,4,8,12

    const long long pbase = (long long)blockIdx.x * (64 * PLM_ITERS);
    const int l  = (int)(pbase / N);
    const int m0 = (int)(pbase - (long long)l * N) + pair;

    const int ul = __ldg(uid + l);

    float* op = out + (long long)N * C_ATOM + (pbase + pair) * C_PAIR + kg;

    // Phase A: batch all uid loads (independent) ...
    int um[PLM_ITERS];
#pragma unroll
    for (int it = 0; it < PLM_ITERS; it++)
        um[it] = __ldg(uid + m0 + it * 64);

    // ... and all zero stores (no dependencies: pure store-issue stream).
    const float4 z = make_float4(0.f, 0.f, 0.f, 0.f);
#pragma unroll
    for (int it = 0; it < PLM_ITERS; it++)
        __stcs(reinterpret_cast<float4*>(op + (long long)it * (64 * C_PAIR)), z);

    // Phase B: rare overwrites (same thread, same address -> ordered).
#pragma unroll
    for (int it = 0; it < PLM_ITERS; it++) {
        if (um[it] == ul) {
            const int m = m0 + it * 64;
            const float d0 = __ldg(pos + l * 3 + 0) - __ldg(pos + m * 3 + 0);
            const float d1 = __ldg(pos + l * 3 + 1) - __ldg(pos + m * 3 + 1);
            const float d2 = __ldg(pos + l * 3 + 2) - __ldg(pos + m * 3 + 2);
            float s = fmaf(d0, d0, 1.0f);
            s = fmaf(d1, d1, s);
            s = fmaf(d2, d2, s);
            const float inv = __fdividef(1.0f, s);

            float4 r;
#pragma unroll
            for (int q = 0; q < 4; q++) {
                const int c = kg + q;
                float t = __ldg(boff + c) + __ldg(binv + c)
                        + __ldg(Wvm + c) + __ldg(bvm + c);
                t = fmaf(d0,  __ldg(Woff + c),              t);
                t = fmaf(d1,  __ldg(Woff + C_PAIR + c),     t);
                t = fmaf(d2,  __ldg(Woff + 2 * C_PAIR + c), t);
                t = fmaf(inv, __ldg(Winv + c),              t);
                (&r.x)[q] = t;
            }
            __stcs(reinterpret_cast<float4*>(op + (long long)it * (64 * C_PAIR)), r);
        }
    }
}

// ---------------------------------------------------------------------------
// Launch: single kernel; 8192 plm blocks FIRST, then 256 cl blocks.
// ---------------------------------------------------------------------------
extern "C" void kernel_launch(void* const* d_in, const int* in_sizes, int n_in,
                              void* d_out, int out_size)
{
    const float* pos    = (const float*)d_in[0];
    const float* charge = (const float*)d_in[1];
    const float* maskp  = (const float*)d_in[2];
    const float* elem   = (const float*)d_in[3];
    const float* names  = (const float*)d_in[4];
    const int*   uid    = (const int*)  d_in[5];
    const float* Wf     = (const float*)d_in[6];
    const float* bf     = (const float*)d_in[7];
    const float* Woff   = (const float*)d_in[8];
    const float* boff   = (const float*)d_in[9];
    const float* Winv   = (const float*)d_in[10];
    const float* binv   = (const float*)d_in[11];
    const float* Wvm    = (const float*)d_in[12];
    const float* bvm    = (const float*)d_in[13];

    const int N = in_sizes[1];  // B*N with B=1
    float* out = (float*)d_out;

    const long long pairs = (long long)N * N;
    const int plmBlocks = (int)(pairs / (64 * PLM_ITERS));      // 8192
    const int clBlocks  = N / CL_ROWS;                          // 256

    fused_kernel<<<plmBlocks + clBlocks, 256>>>(
        pos, charge, maskp, elem, names, uid, Wf, bf,
        Woff, boff, Winv, binv, Wvm, bvm, out, N, plmBlocks);
}

// round 11
// speedup vs baseline: 1.3573x; 1.2753x over previous
#include <cuda_runtime.h>

#define C_ATOM 128
#define C_REF  389
#define C_PAIR 16
#define CL_ROWS 8          // rows per cl block (8 warps x 1 row)
#define PLM_ITERS 8        // 64 pairs/iter * 8 = 512 pairs/block
#define GROUP 33           // 1 cl block + 32 plm blocks per group

// ---------------------------------------------------------------------------
// Fused kernel (R8 skeleton; cl blocks INTERLEAVED 1-in-33 through the grid).
//
// Block b: if b % 33 == 0 -> cl chunk b/33 (256 total, spread over all waves
//          so each wave is ~97% plm store-stream, ~3% cl).
//          else           -> plm tile (b - b/33 - 1) of 512 pairs.
// plm: 4 threads/pair, float4 streaming stores (512B contiguous per warp op).
//   Phase A: 8 independent uid LDGs + 8 UNCONDITIONAL zero STG.cs.128.
//   Phase B: rare (~0.4%) matching slots recomputed + re-stored by the same
//            thread (program order to same address -> nonzero value wins).
// ---------------------------------------------------------------------------
__global__ void __launch_bounds__(256, 8)
fused_kernel(const float* __restrict__ pos,
             const float* __restrict__ charge,
             const float* __restrict__ mask,
             const float* __restrict__ elem,
             const float* __restrict__ names,
             const int*   __restrict__ uid,
             const float* __restrict__ Wf,
             const float* __restrict__ bf,
             const float* __restrict__ Woff,
             const float* __restrict__ boff,
             const float* __restrict__ Winv,
             const float* __restrict__ binv,
             const float* __restrict__ Wvm,
             const float* __restrict__ bvm,
             float* __restrict__ out, int N)
{
    __shared__ float sf[CL_ROWS][C_REF];

    const int tid = threadIdx.x;
    const int b   = blockIdx.x;
    const int g   = b / GROUP;          // group index
    const int r   = b - g * GROUP;      // 0 -> cl, 1..32 -> plm

    if (r == 0) {
        // ------------------------- cl path (1 per group) --------------------
        const int n0   = g * CL_ROWS;
        const int warp = tid >> 5;
        const int lane = tid & 31;

        for (int idx = tid; idx < CL_ROWS * C_REF; idx += 256) {
            int rr = idx / C_REF;
            int j  = idx - rr * C_REF;
            int n  = n0 + rr;
            float v;
            if (j < 3)        v = pos[n * 3 + j];
            else if (j == 3)  v = charge[n];
            else if (j == 4)  v = mask[n];
            else if (j < 133) v = elem[n * 128 + (j - 5)];
            else              v = names[n * 256 + (j - 133)];
            sf[rr][j] = v;
        }
        __syncthreads();

        const int c4 = lane * 4;
        float4 acc = *reinterpret_cast<const float4*>(bf + c4);

#pragma unroll 4
        for (int j = 0; j < C_REF; j++) {
            float4 w = *reinterpret_cast<const float4*>(Wf + j * C_ATOM + c4);
            float  f = sf[warp][j];
            acc.x = fmaf(w.x, f, acc.x);
            acc.y = fmaf(w.y, f, acc.y);
            acc.z = fmaf(w.z, f, acc.z);
            acc.w = fmaf(w.w, f, acc.w);
        }
        *reinterpret_cast<float4*>(out + (long long)(n0 + warp) * C_ATOM + c4) = acc;
        return;
    }

    // --------------------------- plm path ----------------------------------
    const int plmIdx = 32 * g + (r - 1);   // 0..8191

    const int pair = tid >> 2;           // 0..63
    const int kg   = (tid & 3) * 4;      // 0,4,8,12

    const long long pbase = (long long)plmIdx * (64 * PLM_ITERS);
    const int l  = (int)(pbase / N);
    const int m0 = (int)(pbase - (long long)l * N) + pair;

    const int ul = __ldg(uid + l);

    float* op = out + (long long)N * C_ATOM + (pbase + pair) * C_PAIR + kg;

    // Phase A: batch all uid loads (independent) ...
    int um[PLM_ITERS];
#pragma unroll
    for (int it = 0; it < PLM_ITERS; it++)
        um[it] = __ldg(uid + m0 + it * 64);

    // ... and all zero stores (no dependencies: pure store-issue stream).
    const float4 z = make_float4(0.f, 0.f, 0.f, 0.f);
#pragma unroll
    for (int it = 0; it < PLM_ITERS; it++)
        __stcs(reinterpret_cast<float4*>(op + (long long)it * (64 * C_PAIR)), z);

    // Phase B: rare overwrites (same thread, same address -> ordered).
#pragma unroll
    for (int it = 0; it < PLM_ITERS; it++) {
        if (um[it] == ul) {
            const int m = m0 + it * 64;
            const float d0 = __ldg(pos + l * 3 + 0) - __ldg(pos + m * 3 + 0);
            const float d1 = __ldg(pos + l * 3 + 1) - __ldg(pos + m * 3 + 1);
            const float d2 = __ldg(pos + l * 3 + 2) - __ldg(pos + m * 3 + 2);
            float s = fmaf(d0, d0, 1.0f);
            s = fmaf(d1, d1, s);
            s = fmaf(d2, d2, s);
            const float inv = __fdividef(1.0f, s);

            float4 rr;
#pragma unroll
            for (int q = 0; q < 4; q++) {
                const int c = kg + q;
                float t = __ldg(boff + c) + __ldg(binv + c)
                        + __ldg(Wvm + c) + __ldg(bvm + c);
                t = fmaf(d0,  __ldg(Woff + c),              t);
                t = fmaf(d1,  __ldg(Woff + C_PAIR + c),     t);
                t = fmaf(d2,  __ldg(Woff + 2 * C_PAIR + c), t);
                t = fmaf(inv, __ldg(Winv + c),              t);
                (&rr.x)[q] = t;
            }
            __stcs(reinterpret_cast<float4*>(op + (long long)it * (64 * C_PAIR)), rr);
        }
    }
}

// ---------------------------------------------------------------------------
// Launch: single kernel; 33-block groups (1 cl + 32 plm), 256 groups = 8448.
// ---------------------------------------------------------------------------
extern "C" void kernel_launch(void* const* d_in, const int* in_sizes, int n_in,
                              void* d_out, int out_size)
{
    const float* pos    = (const float*)d_in[0];
    const float* charge = (const float*)d_in[1];
    const float* maskp  = (const float*)d_in[2];
    const float* elem   = (const float*)d_in[3];
    const float* names  = (const float*)d_in[4];
    const int*   uid    = (const int*)  d_in[5];
    const float* Wf     = (const float*)d_in[6];
    const float* bf     = (const float*)d_in[7];
    const float* Woff   = (const float*)d_in[8];
    const float* boff   = (const float*)d_in[9];
    const float* Winv   = (const float*)d_in[10];
    const float* binv   = (const float*)d_in[11];
    const float* Wvm    = (const float*)d_in[12];
    const float* bvm    = (const float*)d_in[13];

    const int N = in_sizes[1];  // B*N with B=1
    float* out = (float*)d_out;

    const long long pairs = (long long)N * N;
    const int plmBlocks = (int)(pairs / (64 * PLM_ITERS));      // 8192
    const int clBlocks  = N / CL_ROWS;                          // 256

    fused_kernel<<<plmBlocks + clBlocks, 256>>>(
        pos, charge, maskp, elem, names, uid, Wf, bf,
        Woff, boff, Winv, binv, Wvm, bvm, out, N);
}

// round 12
// speedup vs baseline: 1.9365x; 1.4267x over previous
#include <cuda_runtime.h>

#define C_ATOM 128
#define C_REF  389
#define C_PAIR 16
#define CL_ROWS 8          // rows per cl block (8 warps x 1 row)
#define PLM_ITERS 8        // 64 pairs/iter * 8 = 512 pairs/block

// ---------------------------------------------------------------------------
// Fused kernel (R8 structure: cl blocks FIRST — they must land in wave 0
// where plm warps hide their L2 latency; any late cl block adds its bare
// ~15us latency to the makespan, as R10/R11 demonstrated).
//
// Blocks [0, clBlocks):  cl = feats @ W_feats + b_feats (8 warps x 1 row),
//   W-loads unrolled x8 with batched __ldg -> MLP 8, ~half the latency
//   exposure of the R8 version.
// Blocks [clBlocks, ..): plm, 512 pairs/block, 4 threads/pair.
//   Phase A: 8 independent uid LDGs + 8 UNCONDITIONAL zero STG.cs.128
//            (dependency-free store stream at memset-like issue rate).
//   Phase B: rare (~0.4%) matching slots recomputed and re-stored by the
//            same thread (program order to same address -> nonzero wins).
// ---------------------------------------------------------------------------
__global__ void __launch_bounds__(256, 8)
fused_kernel(const float* __restrict__ pos,
             const float* __restrict__ charge,
             const float* __restrict__ mask,
             const float* __restrict__ elem,
             const float* __restrict__ names,
             const int*   __restrict__ uid,
             const float* __restrict__ Wf,
             const float* __restrict__ bf,
             const float* __restrict__ Woff,
             const float* __restrict__ boff,
             const float* __restrict__ Winv,
             const float* __restrict__ binv,
             const float* __restrict__ Wvm,
             const float* __restrict__ bvm,
             float* __restrict__ out, int N, int clBlocks)
{
    __shared__ float sf[CL_ROWS][C_REF + 3];   // +3 pad: full unroll-8 reads

    const int tid = threadIdx.x;

    if (blockIdx.x < (unsigned)clBlocks) {
        // ------------------------- cl path ---------------------------------
        const int n0   = blockIdx.x * CL_ROWS;
        const int warp = tid >> 5;
        const int lane = tid & 31;

        for (int idx = tid; idx < CL_ROWS * C_REF; idx += 256) {
            int r = idx / C_REF;
            int j = idx - r * C_REF;
            int n = n0 + r;
            float v;
            if (j < 3)        v = pos[n * 3 + j];
            else if (j == 3)  v = charge[n];
            else if (j == 4)  v = mask[n];
            else if (j < 133) v = elem[n * 128 + (j - 5)];
            else              v = names[n * 256 + (j - 133)];
            sf[r][j] = v;
        }
        __syncthreads();

        const int c4 = lane * 4;
        float4 acc = *reinterpret_cast<const float4*>(bf + c4);
        const float4* Wp = reinterpret_cast<const float4*>(Wf) + lane;

        // Main loop: batches of 8 W rows -> 8 outstanding LDG.128 (MLP 8).
        int j = 0;
        for (; j + 8 <= C_REF; j += 8) {
            float4 w[8];
#pragma unroll
            for (int q = 0; q < 8; q++)
                w[q] = __ldg(Wp + (j + q) * (C_ATOM / 4));
#pragma unroll
            for (int q = 0; q < 8; q++) {
                const float f = sf[warp][j + q];
                acc.x = fmaf(w[q].x, f, acc.x);
                acc.y = fmaf(w[q].y, f, acc.y);
                acc.z = fmaf(w[q].z, f, acc.z);
                acc.w = fmaf(w[q].w, f, acc.w);
            }
        }
        for (; j < C_REF; j++) {   // 389 % 8 = 5 tail rows
            const float4 w = __ldg(Wp + j * (C_ATOM / 4));
            const float  f = sf[warp][j];
            acc.x = fmaf(w.x, f, acc.x);
            acc.y = fmaf(w.y, f, acc.y);
            acc.z = fmaf(w.z, f, acc.z);
            acc.w = fmaf(w.w, f, acc.w);
        }

        *reinterpret_cast<float4*>(out + (long long)(n0 + warp) * C_ATOM + c4) = acc;
        return;
    }

    // --------------------------- plm path ----------------------------------
    const int pair = tid >> 2;           // 0..63
    const int kg   = (tid & 3) * 4;      // 0,4,8,12

    const long long pbase = (long long)(blockIdx.x - clBlocks) * (64 * PLM_ITERS);
    const int l  = (int)(pbase / N);
    const int m0 = (int)(pbase - (long long)l * N) + pair;

    const int ul = __ldg(uid + l);

    float* op = out + (long long)N * C_ATOM + (pbase + pair) * C_PAIR + kg;

    // Phase A: batch all uid loads (independent) ...
    int um[PLM_ITERS];
#pragma unroll
    for (int it = 0; it < PLM_ITERS; it++)
        um[it] = __ldg(uid + m0 + it * 64);

    // ... and all zero stores (no dependencies: pure store-issue stream).
    const float4 z = make_float4(0.f, 0.f, 0.f, 0.f);
#pragma unroll
    for (int it = 0; it < PLM_ITERS; it++)
        __stcs(reinterpret_cast<float4*>(op + (long long)it * (64 * C_PAIR)), z);

    // Phase B: rare overwrites (same thread, same address -> ordered).
#pragma unroll
    for (int it = 0; it < PLM_ITERS; it++) {
        if (um[it] == ul) {
            const int m = m0 + it * 64;
            const float d0 = __ldg(pos + l * 3 + 0) - __ldg(pos + m * 3 + 0);
            const float d1 = __ldg(pos + l * 3 + 1) - __ldg(pos + m * 3 + 1);
            const float d2 = __ldg(pos + l * 3 + 2) - __ldg(pos + m * 3 + 2);
            float s = fmaf(d0, d0, 1.0f);
            s = fmaf(d1, d1, s);
            s = fmaf(d2, d2, s);
            const float inv = __fdividef(1.0f, s);

            float4 r;
#pragma unroll
            for (int q = 0; q < 4; q++) {
                const int c = kg + q;
                float t = __ldg(boff + c) + __ldg(binv + c)
                        + __ldg(Wvm + c) + __ldg(bvm + c);
                t = fmaf(d0,  __ldg(Woff + c),              t);
                t = fmaf(d1,  __ldg(Woff + C_PAIR + c),     t);
                t = fmaf(d2,  __ldg(Woff + 2 * C_PAIR + c), t);
                t = fmaf(inv, __ldg(Winv + c),              t);
                (&r.x)[q] = t;
            }
            __stcs(reinterpret_cast<float4*>(op + (long long)it * (64 * C_PAIR)), r);
        }
    }
}

// ---------------------------------------------------------------------------
// Launch: single kernel; 256 cl blocks FIRST (wave 0), then 8192 plm blocks.
// ---------------------------------------------------------------------------
extern "C" void kernel_launch(void* const* d_in, const int* in_sizes, int n_in,
                              void* d_out, int out_size)
{
    const float* pos    = (const float*)d_in[0];
    const float* charge = (const float*)d_in[1];
    const float* maskp  = (const float*)d_in[2];
    const float* elem   = (const float*)d_in[3];
    const float* names  = (const float*)d_in[4];
    const int*   uid    = (const int*)  d_in[5];
    const float* Wf     = (const float*)d_in[6];
    const float* bf     = (const float*)d_in[7];
    const float* Woff   = (const float*)d_in[8];
    const float* boff   = (const float*)d_in[9];
    const float* Winv   = (const float*)d_in[10];
    const float* binv   = (const float*)d_in[11];
    const float* Wvm    = (const float*)d_in[12];
    const float* bvm    = (const float*)d_in[13];

    const int N = in_sizes[1];  // B*N with B=1
    float* out = (float*)d_out;

    const int clBlocks = N / CL_ROWS;                           // 256
    const long long pairs = (long long)N * N;
    const int plmBlocks = (int)(pairs / (64 * PLM_ITERS));      // 8192

    fused_kernel<<<clBlocks + plmBlocks, 256>>>(
        pos, charge, maskp, elem, names, uid, Wf, bf,
        Woff, boff, Winv, binv, Wvm, bvm, out, N, clBlocks);
}

// round 13
// speedup vs baseline: 2.0092x; 1.0376x over previous
#include <cuda_runtime.h>

#define C_ATOM 128
#define C_REF  389
#define C_PAIR 16
#define CL_ROWS 8          // rows per cl block (8 warps x 1 row)
#define PLM_ITERS 4        // 64 pairs/iter * 4 = 256 pairs/block

// ---------------------------------------------------------------------------
// Fused kernel (R8 winner structure; only change: PLM_ITERS 8 -> 4 to halve
// the final-wave tail quantum; cl path reverted to the R8 version).
//
// Blocks [0, clBlocks):  cl = feats @ W_feats + b_feats (8 warps x 1 row).
//   cl blocks MUST be first: in wave 0 their L2 latency hides under plm
//   warps; any late cl block adds its bare ~15us to the makespan (R10/R11).
// Blocks [clBlocks, ..): plm, 256 pairs/block, 4 threads/pair.
//   Phase A: 4 independent uid LDGs + 4 UNCONDITIONAL zero STG.cs.128
//            (dependency-free store stream at memset-like issue rate).
//   Phase B: rare (~0.4%) matching slots recomputed and re-stored by the
//            same thread (program order to same address -> nonzero wins).
// ---------------------------------------------------------------------------
__global__ void __launch_bounds__(256, 8)
fused_kernel(const float* __restrict__ pos,
             const float* __restrict__ charge,
             const float* __restrict__ mask,
             const float* __restrict__ elem,
             const float* __restrict__ names,
             const int*   __restrict__ uid,
             const float* __restrict__ Wf,
             const float* __restrict__ bf,
             const float* __restrict__ Woff,
             const float* __restrict__ boff,
             const float* __restrict__ Winv,
             const float* __restrict__ binv,
             const float* __restrict__ Wvm,
             const float* __restrict__ bvm,
             float* __restrict__ out, int N, int clBlocks)
{
    __shared__ float sf[CL_ROWS][C_REF];

    const int tid = threadIdx.x;

    if (blockIdx.x < (unsigned)clBlocks) {
        // ------------------------- cl path (R8 version) ---------------------
        const int n0   = blockIdx.x * CL_ROWS;
        const int warp = tid >> 5;
        const int lane = tid & 31;

        for (int idx = tid; idx < CL_ROWS * C_REF; idx += 256) {
            int r = idx / C_REF;
            int j = idx - r * C_REF;
            int n = n0 + r;
            float v;
            if (j < 3)        v = pos[n * 3 + j];
            else if (j == 3)  v = charge[n];
            else if (j == 4)  v = mask[n];
            else if (j < 133) v = elem[n * 128 + (j - 5)];
            else              v = names[n * 256 + (j - 133)];
            sf[r][j] = v;
        }
        __syncthreads();

        const int c4 = lane * 4;
        float4 acc = *reinterpret_cast<const float4*>(bf + c4);

#pragma unroll 4
        for (int j = 0; j < C_REF; j++) {
            float4 w = *reinterpret_cast<const float4*>(Wf + j * C_ATOM + c4);
            float  f = sf[warp][j];
            acc.x = fmaf(w.x, f, acc.x);
            acc.y = fmaf(w.y, f, acc.y);
            acc.z = fmaf(w.z, f, acc.z);
            acc.w = fmaf(w.w, f, acc.w);
        }
        *reinterpret_cast<float4*>(out + (long long)(n0 + warp) * C_ATOM + c4) = acc;
        return;
    }

    // --------------------------- plm path ----------------------------------
    const int pair = tid >> 2;           // 0..63
    const int kg   = (tid & 3) * 4;      // 0,4,8,12

    const long long pbase = (long long)(blockIdx.x - clBlocks) * (64 * PLM_ITERS);
    const int l  = (int)(pbase / N);
    const int m0 = (int)(pbase - (long long)l * N) + pair;

    const int ul = __ldg(uid + l);

    float* op = out + (long long)N * C_ATOM + (pbase + pair) * C_PAIR + kg;

    // Phase A: batch all uid loads (independent) ...
    int um[PLM_ITERS];
#pragma unroll
    for (int it = 0; it < PLM_ITERS; it++)
        um[it] = __ldg(uid + m0 + it * 64);

    // ... and all zero stores (no dependencies: pure store-issue stream).
    const float4 z = make_float4(0.f, 0.f, 0.f, 0.f);
#pragma unroll
    for (int it = 0; it < PLM_ITERS; it++)
        __stcs(reinterpret_cast<float4*>(op + (long long)it * (64 * C_PAIR)), z);

    // Phase B: rare overwrites (same thread, same address -> ordered).
#pragma unroll
    for (int it = 0; it < PLM_ITERS; it++) {
        if (um[it] == ul) {
            const int m = m0 + it * 64;
            const float d0 = __ldg(pos + l * 3 + 0) - __ldg(pos + m * 3 + 0);
            const float d1 = __ldg(pos + l * 3 + 1) - __ldg(pos + m * 3 + 1);
            const float d2 = __ldg(pos + l * 3 + 2) - __ldg(pos + m * 3 + 2);
            float s = fmaf(d0, d0, 1.0f);
            s = fmaf(d1, d1, s);
            s = fmaf(d2, d2, s);
            const float inv = __fdividef(1.0f, s);

            float4 r;
#pragma unroll
            for (int q = 0; q < 4; q++) {
                const int c = kg + q;
                float t = __ldg(boff + c) + __ldg(binv + c)
                        + __ldg(Wvm + c) + __ldg(bvm + c);
                t = fmaf(d0,  __ldg(Woff + c),              t);
                t = fmaf(d1,  __ldg(Woff + C_PAIR + c),     t);
                t = fmaf(d2,  __ldg(Woff + 2 * C_PAIR + c), t);
                t = fmaf(inv, __ldg(Winv + c),              t);
                (&r.x)[q] = t;
            }
            __stcs(reinterpret_cast<float4*>(op + (long long)it * (64 * C_PAIR)), r);
        }
    }
}

// ---------------------------------------------------------------------------
// Launch: single kernel; 256 cl blocks FIRST (wave 0), then 16384 plm blocks.
// ---------------------------------------------------------------------------
extern "C" void kernel_launch(void* const* d_in, const int* in_sizes, int n_in,
                              void* d_out, int out_size)
{
    const float* pos    = (const float*)d_in[0];
    const float* charge = (const float*)d_in[1];
    const float* maskp  = (const float*)d_in[2];
    const float* elem   = (const float*)d_in[3];
    const float* names  = (const float*)d_in[4];
    const int*   uid    = (const int*)  d_in[5];
    const float* Wf     = (const float*)d_in[6];
    const float* bf     = (const float*)d_in[7];
    const float* Woff   = (const float*)d_in[8];
    const float* boff   = (const float*)d_in[9];
    const float* Winv   = (const float*)d_in[10];
    const float* binv   = (const float*)d_in[11];
    const float* Wvm    = (const float*)d_in[12];
    const float* bvm    = (const float*)d_in[13];

    const int N = in_sizes[1];  // B*N with B=1
    float* out = (float*)d_out;

    const int clBlocks = N / CL_ROWS;                           // 256
    const long long pairs = (long long)N * N;
    const int plmBlocks = (int)(pairs / (64 * PLM_ITERS));      // 16384

    fused_kernel<<<clBlocks + plmBlocks, 256>>>(
        pos, charge, maskp, elem, names, uid, Wf, bf,
        Woff, boff, Winv, binv, Wvm, bvm, out, N, clBlocks);
}